// round 12
// baseline (speedup 1.0000x reference)
#include <cuda_runtime.h>
#include <cuda_fp16.h>
#include <cstdint>

#define NQ 16384
#define DM 256
#define DFF_ 1024
#define LN_EPS 1e-5f

// ---------------------------------------------------------------------------
// scratch
// ---------------------------------------------------------------------------
__device__ float g_f32[2u * NQ * DM];          // t2, x
__device__ __half g_qkv[3u * NQ * DM];         // q, k, v

// fp16 pool (element offsets)
#define OFF_TGT 0u
#define OFF_MEM 4194304u
#define OFF_POS 8388608u
#define OFF_AT  12582912u
#define OFF_X   16777216u
#define OFF_H   20971520u
#define OFF_WQ  37748736u
#define OFF_WKC 37814272u
#define OFF_WKP 37879808u
#define OFF_WV  37945344u
#define OFF_WO  38010880u
#define OFF_W1  38076416u
#define OFF_W2  38338560u
#define TOT_H16 38600704u
__device__ __half g_h16[TOT_H16];

// ---------------------------------------------------------------------------
// helpers
// ---------------------------------------------------------------------------
__device__ __forceinline__ uint32_t smem_u32(const void* p) {
    uint32_t a;
    asm("{ .reg .u64 t; cvta.to.shared.u64 t, %1; cvt.u32.u64 %0, t; }"
        : "=r"(a) : "l"(p));
    return a;
}
__device__ __forceinline__ void cpa16(uint32_t dst, const void* src) {
    asm volatile("cp.async.cg.shared.global [%0], [%1], 16;"
                 :: "r"(dst), "l"(src) : "memory");
}
#define CP_COMMIT() asm volatile("cp.async.commit_group;" ::: "memory")
#define CP_WAIT(n)  asm volatile("cp.async.wait_group %0;" :: "n"(n) : "memory")

#define LDSM4(r, addr) \
    asm volatile("ldmatrix.sync.aligned.m8n8.x4.shared.b16 {%0,%1,%2,%3}, [%4];" \
        : "=r"((r)[0]), "=r"((r)[1]), "=r"((r)[2]), "=r"((r)[3]) : "r"(addr))

#define MMA_F16(d, a, b0, b1) \
    asm volatile("mma.sync.aligned.m16n8k16.row.col.f32.f16.f16.f32 " \
        "{%0,%1,%2,%3}, {%4,%5,%6,%7}, {%8,%9}, {%0,%1,%2,%3};" \
        : "+f"((d)[0]), "+f"((d)[1]), "+f"((d)[2]), "+f"((d)[3]) \
        : "r"((a)[0]), "r"((a)[1]), "r"((a)[2]), "r"((a)[3]), "r"(b0), "r"(b1))

// swizzled smem byte offset for (row, chunk16B) with 64B rows (BK=32 fp16)
__device__ __forceinline__ uint32_t swzoff(int row, int ch) {
    return (uint32_t)(row * 64 + ((ch ^ ((row >> 1) & 3)) << 4));
}

__device__ __forceinline__ uint32_t pack2(float a, float b) {
    __half2 p;
    p.x = __float2half_rn(a);
    p.y = __float2half_rn(b);
    return *(uint32_t*)&p;
}

#define PART_SZ 8192u                // 128 rows * 64B
#define STAGE_SZ 16384u              // A + W
#define NSTAGE 4
#define SMEM_BYTES (NSTAGE * STAGE_SZ)   // 65536

// ---------------------------------------------------------------------------
// GEMM core (512 threads, 16 warps of 32x32): acc += A[bm:+128,:K] @ W[bn:+128,:K]^T
// 4-stage cp.async pipeline.  Each thread loads exactly one 16B per operand/chunk.
// ---------------------------------------------------------------------------
template <int CHUNKS>
__device__ __forceinline__ void gemm_core(
    uint32_t sbase, const __half* __restrict__ A, const __half* __restrict__ W,
    int bm, int bn, int tid, int wm, int wn, int lane, float (&acc)[2][4][4])
{
    constexpr int K = CHUNKS * 32;
    __syncthreads();   // protect smem reuse from a previous pass

    const int lrow = tid >> 2;
    const int lch = tid & 3;

    auto load = [&](int c) {
        const uint32_t stage = sbase + (uint32_t)(c % NSTAGE) * STAGE_SZ;
        cpa16(stage + swzoff(lrow, lch),
              A + (size_t)(bm + lrow) * K + c * 32 + lch * 8);
        cpa16(stage + PART_SZ + swzoff(lrow, lch),
              W + (size_t)(bn + lrow) * K + c * 32 + lch * 8);
        CP_COMMIT();
    };

    auto comp = [&](int s) {
        const uint32_t stage = sbase + (uint32_t)s * STAGE_SZ;
#pragma unroll
        for (int ks = 0; ks < 2; ++ks) {
            const int ch = ks * 2 + (lane >> 4);
            uint32_t af[2][4], bf[2][4];
#pragma unroll
            for (int mt = 0; mt < 2; ++mt)
                LDSM4(af[mt], stage + swzoff(wm + mt * 16 + (lane & 15), ch));
#pragma unroll
            for (int np = 0; np < 2; ++np)
                LDSM4(bf[np], stage + PART_SZ + swzoff(wn + np * 16 + (lane & 15), ch));
#pragma unroll
            for (int mt = 0; mt < 2; ++mt) {
#pragma unroll
                for (int nt = 0; nt < 4; ++nt) {
                    const int np = nt >> 1;
                    const int o0 = (nt & 1);
                    MMA_F16(acc[mt][nt], af[mt], bf[np][o0], bf[np][o0 + 2]);
                }
            }
        }
    };

#pragma unroll
    for (int c = 0; c < NSTAGE - 1; ++c) load(c);
#pragma unroll
    for (int c = 0; c < CHUNKS; ++c) {
        const int rem = CHUNKS - 1 - c;
        if (rem >= 2) { CP_WAIT(2); }
        else if (rem == 1) { CP_WAIT(1); }
        else { CP_WAIT(0); }
        __syncthreads();
        if (c + NSTAGE - 1 < CHUNKS) load(c + NSTAGE - 1);
        comp(c % NSTAGE);
    }
}

// epilogue: acc + bias (+bias2) [+relu] -> fp32 or fp16
template <bool RELU, int OUTMODE>
__device__ __forceinline__ void epilogue(
    float (&acc)[2][4][4], const float* __restrict__ bias,
    const float* __restrict__ bias2, float* __restrict__ C,
    __half* __restrict__ Ch, int bm, int bn, int wm, int wn, int lane, int Nout)
{
    float bcol[4][2];
#pragma unroll
    for (int nt = 0; nt < 4; ++nt) {
        int col = bn + wn + nt * 8 + (lane & 3) * 2;
        float b0 = bias[col], b1 = bias[col + 1];
        if (bias2) { b0 += bias2[col]; b1 += bias2[col + 1]; }
        bcol[nt][0] = b0; bcol[nt][1] = b1;
    }
#pragma unroll
    for (int mt = 0; mt < 2; ++mt) {
        int row0 = bm + wm + mt * 16 + (lane >> 2);
#pragma unroll
        for (int nt = 0; nt < 4; ++nt) {
            int col = bn + wn + nt * 8 + (lane & 3) * 2;
#pragma unroll
            for (int half = 0; half < 2; ++half) {
                int row = row0 + half * 8;
                float v0 = acc[mt][nt][half * 2 + 0] + bcol[nt][0];
                float v1 = acc[mt][nt][half * 2 + 1] + bcol[nt][1];
                if (RELU) { v0 = fmaxf(v0, 0.f); v1 = fmaxf(v1, 0.f); }
                size_t go = (size_t)row * Nout + col;
                if (OUTMODE == 1) {
                    *(uint32_t*)(Ch + go) = pack2(v0, v1);
                } else {
                    *(float2*)(C + go) = make_float2(v0, v1);
                }
            }
        }
    }
}

// ---------------------------------------------------------------------------
// Fused q/k/v projection: grid (2, 128, 3); z selects q, k(dual), v. 512 thr.
// ---------------------------------------------------------------------------
__global__ __launch_bounds__(512, 2)
void qkv_mma(const __half* __restrict__ tgtH, const __half* __restrict__ memH,
             const __half* __restrict__ posH,
             const __half* __restrict__ WqH, const __half* __restrict__ WkcH,
             const __half* __restrict__ WkpH, const __half* __restrict__ WvH,
             const float* __restrict__ bq, const float* __restrict__ bkc,
             const float* __restrict__ bkp, const float* __restrict__ bv,
             __half* __restrict__ q_, __half* __restrict__ k_,
             __half* __restrict__ v_)
{
    extern __shared__ char smem[];
    const uint32_t sbase = smem_u32(smem);
    const int tid = threadIdx.x;
    const int wid = tid >> 5;
    const int lane = tid & 31;
    const int bm = blockIdx.y * 128;
    const int bn = blockIdx.x * 128;
    const int wm = (wid & 3) * 32;
    const int wn = (wid >> 2) * 32;
    const int z = blockIdx.z;

    float acc[2][4][4];
#pragma unroll
    for (int a = 0; a < 2; ++a)
#pragma unroll
        for (int b = 0; b < 4; ++b)
#pragma unroll
            for (int c = 0; c < 4; ++c) acc[a][b][c] = 0.f;

    const __half* A = (z == 0) ? tgtH : memH;
    const __half* W = (z == 0) ? WqH : (z == 1) ? WkcH : WvH;
    gemm_core<8>(sbase, A, W, bm, bn, tid, wm, wn, lane, acc);
    if (z == 1)
        gemm_core<8>(sbase, posH, WkpH, bm, bn, tid, wm, wn, lane, acc);

    const float* bias = (z == 0) ? bq : (z == 1) ? bkc : bv;
    const float* bias2 = (z == 1) ? bkp : nullptr;
    __half* out = (z == 0) ? q_ : (z == 1) ? k_ : v_;
    epilogue<false, 1>(acc, bias, bias2, nullptr, out, bm, bn, wm, wn, lane, DM);
}

// ---------------------------------------------------------------------------
// Generic GEMM launch: C = A@W^T + bias  (512 threads)
// ---------------------------------------------------------------------------
template <int CHUNKS, bool RELU, int OUTMODE>
__global__ __launch_bounds__(512, 2)
void gemm_k(const __half* __restrict__ A, const __half* __restrict__ W,
            const float* __restrict__ bias,
            float* __restrict__ C, __half* __restrict__ Ch, int Nout)
{
    extern __shared__ char smem[];
    const uint32_t sbase = smem_u32(smem);
    const int tid = threadIdx.x;
    const int wid = tid >> 5;
    const int lane = tid & 31;
    const int bm = blockIdx.y * 128;
    const int bn = blockIdx.x * 128;
    const int wm = (wid & 3) * 32;
    const int wn = (wid >> 2) * 32;

    float acc[2][4][4];
#pragma unroll
    for (int a = 0; a < 2; ++a)
#pragma unroll
        for (int b = 0; b < 4; ++b)
#pragma unroll
            for (int c = 0; c < 4; ++c) acc[a][b][c] = 0.f;

    gemm_core<CHUNKS>(sbase, A, W, bm, bn, tid, wm, wn, lane, acc);
    epilogue<RELU, OUTMODE>(acc, bias, nullptr, C, Ch, bm, bn, wm, wn, lane, Nout);
}

// ---------------------------------------------------------------------------
// Conversion: fp32 -> fp16, 10 tensors via blockIdx.y, 8 elems/thread
// ---------------------------------------------------------------------------
__global__ __launch_bounds__(256)
void conv_all(const float* s0, const float* s1, const float* s2, const float* s3,
              const float* s4, const float* s5, const float* s6, const float* s7,
              const float* s8, const float* s9, __half* dst)
{
    const int t = blockIdx.y;
    const unsigned narr[10] = {4194304u, 4194304u, 4194304u, 65536u, 65536u,
                               65536u, 65536u, 65536u, 262144u, 262144u};
    const unsigned offarr[10] = {OFF_TGT, OFF_MEM, OFF_POS, OFF_WQ, OFF_WKC,
                                 OFF_WKP, OFF_WV, OFF_WO, OFF_W1, OFF_W2};
    const float* srcs[10] = {s0, s1, s2, s3, s4, s5, s6, s7, s8, s9};
    unsigned i = (blockIdx.x * 256u + threadIdx.x) * 8u;
    if (i >= narr[t]) return;
    const float* src = srcs[t];
    float4 v0 = *(const float4*)(src + i);
    float4 v1 = *(const float4*)(src + i + 4);
    uint4 o;
    o.x = pack2(v0.x, v0.y);
    o.y = pack2(v0.z, v0.w);
    o.z = pack2(v1.x, v1.y);
    o.w = pack2(v1.z, v1.w);
    *(uint4*)(dst + offarr[t] + i) = o;
}

// ---------------------------------------------------------------------------
// Local attention: one warp per query; q/k/v fp16, output fp16.
// Gather loads batched by 8 to maximize memory-level parallelism.
// ---------------------------------------------------------------------------
__global__ __launch_bounds__(256, 2)
void attn_kernel(const __half* __restrict__ q, const __half* __restrict__ k,
                 const __half* __restrict__ v, const int* __restrict__ kbc,
                 const int* __restrict__ ipair, const int* __restrict__ ibatch,
                 __half* __restrict__ oat)
{
    __shared__ int sg[8][32];
    const int warp = threadIdx.x >> 5;
    const int lane = threadIdx.x & 31;
    const int n = blockIdx.x * 8 + warp;
    const int h = lane >> 2;
    const int s = lane & 3;
    const int doff = h * 32 + s * 8;

    int b = ibatch[n];
    int off = 0;
    for (int i = 0; i < b; ++i) off += kbc[i];

    int idx = ipair[n * 32 + lane];
    unsigned mb = __ballot_sync(0xffffffffu, idx < 0);
    sg[warp][lane] = ((idx < 0) ? 0 : idx) + off;
    __syncwarp();

    const float scale = 0.17677669529663687f;
    float qr[8];
    {
        uint4 raw = *(const uint4*)&q[(size_t)n * 256 + doff];
        float2 a0 = __half22float2(*(__half2*)&raw.x);
        float2 a1 = __half22float2(*(__half2*)&raw.y);
        float2 a2 = __half22float2(*(__half2*)&raw.z);
        float2 a3 = __half22float2(*(__half2*)&raw.w);
        qr[0] = a0.x * scale; qr[1] = a0.y * scale;
        qr[2] = a1.x * scale; qr[3] = a1.y * scale;
        qr[4] = a2.x * scale; qr[5] = a2.y * scale;
        qr[6] = a3.x * scale; qr[7] = a3.y * scale;
    }

    float lg[32];
#pragma unroll
    for (int jb = 0; jb < 32; jb += 8) {
        uint4 raw[8];
#pragma unroll
        for (int u = 0; u < 8; ++u)
            raw[u] = *(const uint4*)&k[(size_t)sg[warp][jb + u] * 256 + doff];
#pragma unroll
        for (int u = 0; u < 8; ++u) {
            float2 a0 = __half22float2(*(__half2*)&raw[u].x);
            float2 a1 = __half22float2(*(__half2*)&raw[u].y);
            float2 a2 = __half22float2(*(__half2*)&raw[u].z);
            float2 a3 = __half22float2(*(__half2*)&raw[u].w);
            float t = qr[0] * a0.x + qr[1] * a0.y + qr[2] * a1.x + qr[3] * a1.y
                    + qr[4] * a2.x + qr[5] * a2.y + qr[6] * a3.x + qr[7] * a3.y;
            t += __shfl_xor_sync(0xffffffffu, t, 1);
            t += __shfl_xor_sync(0xffffffffu, t, 2);
            lg[jb + u] = ((mb >> (jb + u)) & 1u) ? -1e9f : t;
        }
    }

    float m = lg[0];
#pragma unroll
    for (int j = 1; j < 32; ++j) m = fmaxf(m, lg[j]);
    float sum = 0.f;
#pragma unroll
    for (int j = 0; j < 32; ++j) { lg[j] = __expf(lg[j] - m); sum += lg[j]; }
    float rinv = 1.f / sum;

    float acc[8];
#pragma unroll
    for (int i = 0; i < 8; ++i) acc[i] = 0.f;
#pragma unroll
    for (int jb = 0; jb < 32; jb += 8) {
        uint4 raw[8];
#pragma unroll
        for (int u = 0; u < 8; ++u)
            raw[u] = *(const uint4*)&v[(size_t)sg[warp][jb + u] * 256 + doff];
#pragma unroll
        for (int u = 0; u < 8; ++u) {
            float2 a0 = __half22float2(*(__half2*)&raw[u].x);
            float2 a1 = __half22float2(*(__half2*)&raw[u].y);
            float2 a2 = __half22float2(*(__half2*)&raw[u].z);
            float2 a3 = __half22float2(*(__half2*)&raw[u].w);
            float p = lg[jb + u] * rinv;
            acc[0] += p * a0.x; acc[1] += p * a0.y;
            acc[2] += p * a1.x; acc[3] += p * a1.y;
            acc[4] += p * a2.x; acc[5] += p * a2.y;
            acc[6] += p * a3.x; acc[7] += p * a3.y;
        }
    }

    uint4 o;
    o.x = pack2(acc[0], acc[1]);
    o.y = pack2(acc[2], acc[3]);
    o.z = pack2(acc[4], acc[5]);
    o.w = pack2(acc[6], acc[7]);
    *(uint4*)(oat + (size_t)n * 256 + doff) = o;
}

// ---------------------------------------------------------------------------
// out = LayerNorm(a + b); optionally also writes fp16 copy.
// ---------------------------------------------------------------------------
template <bool OUTH>
__global__ __launch_bounds__(256)
void residual_ln(const float* __restrict__ a, const float* __restrict__ bsrc,
                 const float* __restrict__ g, const float* __restrict__ be,
                 float* __restrict__ out, __half* __restrict__ oh)
{
    const int warp = threadIdx.x >> 5;
    const int lane = threadIdx.x & 31;
    const int n = blockIdx.x * 8 + warp;
    const int base = lane * 8;

    float x[8];
    {
        const float4* pa0 = (const float4*)&a[(size_t)n * 256 + base];
        const float4* pb0 = (const float4*)&bsrc[(size_t)n * 256 + base];
        float4 a0 = pa0[0], a1 = pa0[1];
        float4 b0 = pb0[0], b1 = pb0[1];
        x[0] = a0.x + b0.x; x[1] = a0.y + b0.y; x[2] = a0.z + b0.z; x[3] = a0.w + b0.w;
        x[4] = a1.x + b1.x; x[5] = a1.y + b1.y; x[6] = a1.z + b1.z; x[7] = a1.w + b1.w;
    }
    float s = 0.f;
#pragma unroll
    for (int i = 0; i < 8; ++i) s += x[i];
#pragma unroll
    for (int o = 16; o > 0; o >>= 1) s += __shfl_xor_sync(0xffffffffu, s, o);
    float mean = s * (1.f / 256.f);

    float vs = 0.f;
#pragma unroll
    for (int i = 0; i < 8; ++i) { float d = x[i] - mean; vs += d * d; }
#pragma unroll
    for (int o = 16; o > 0; o >>= 1) vs += __shfl_xor_sync(0xffffffffu, vs, o);
    float inv = rsqrtf(vs * (1.f / 256.f) + LN_EPS);

    float4 gg0 = *(const float4*)&g[base];
    float4 gg1 = *(const float4*)&g[base + 4];
    float4 bb0 = *(const float4*)&be[base];
    float4 bb1 = *(const float4*)&be[base + 4];

    float r[8];
    r[0] = (x[0] - mean) * inv * gg0.x + bb0.x;
    r[1] = (x[1] - mean) * inv * gg0.y + bb0.y;
    r[2] = (x[2] - mean) * inv * gg0.z + bb0.z;
    r[3] = (x[3] - mean) * inv * gg0.w + bb0.w;
    r[4] = (x[4] - mean) * inv * gg1.x + bb1.x;
    r[5] = (x[5] - mean) * inv * gg1.y + bb1.y;
    r[6] = (x[6] - mean) * inv * gg1.z + bb1.z;
    r[7] = (x[7] - mean) * inv * gg1.w + bb1.w;

    size_t o = (size_t)n * 256 + base;
    *(float4*)(out + o) = make_float4(r[0], r[1], r[2], r[3]);
    *(float4*)(out + o + 4) = make_float4(r[4], r[5], r[6], r[7]);

    if (OUTH) {
        uint4 p;
        p.x = pack2(r[0], r[1]);
        p.y = pack2(r[2], r[3]);
        p.z = pack2(r[4], r[5]);
        p.w = pack2(r[6], r[7]);
        *(uint4*)(oh + o) = p;
    }
}

// ---------------------------------------------------------------------------
extern "C" void kernel_launch(void* const* d_in, const int* in_sizes, int n_in,
                              void* d_out, int out_size)
{
    const float* tgt  = (const float*)d_in[0];
    const float* mem  = (const float*)d_in[1];
    const float* pos  = (const float*)d_in[2];
    const int*   kbc  = (const int*)d_in[3];
    const int*   ipair  = (const int*)d_in[4];
    const int*   ibatch = (const int*)d_in[5];
    const float* Wq  = (const float*)d_in[6];
    const float* bq  = (const float*)d_in[7];
    const float* Wkc = (const float*)d_in[8];
    const float* bkc = (const float*)d_in[9];
    const float* Wkp = (const float*)d_in[10];
    const float* bkp = (const float*)d_in[11];
    const float* Wv  = (const float*)d_in[12];
    const float* bv  = (const float*)d_in[13];
    const float* Wo  = (const float*)d_in[14];
    const float* bo  = (const float*)d_in[15];
    const float* W1  = (const float*)d_in[16];
    const float* b1  = (const float*)d_in[17];
    const float* W2  = (const float*)d_in[18];
    const float* b2  = (const float*)d_in[19];
    const float* g2  = (const float*)d_in[20];
    const float* be2 = (const float*)d_in[21];
    const float* g3  = (const float*)d_in[22];
    const float* be3 = (const float*)d_in[23];
    float* out = (float*)d_out;

    float* f32 = nullptr;
    __half* qkv = nullptr;
    __half* h16 = nullptr;
    cudaGetSymbolAddress((void**)&f32, g_f32);
    cudaGetSymbolAddress((void**)&qkv, g_qkv);
    cudaGetSymbolAddress((void**)&h16, g_h16);

    float* t2_ = f32 + 0u * NQ * DM;
    float* x_  = f32 + 1u * NQ * DM;
    __half* q_ = qkv + 0u * NQ * DM;
    __half* k_ = qkv + 1u * NQ * DM;
    __half* v_ = qkv + 2u * NQ * DM;

    cudaFuncSetAttribute(qkv_mma,
                         cudaFuncAttributeMaxDynamicSharedMemorySize, SMEM_BYTES);
    cudaFuncSetAttribute(gemm_k<8, false, 0>,
                         cudaFuncAttributeMaxDynamicSharedMemorySize, SMEM_BYTES);
    cudaFuncSetAttribute(gemm_k<8, true, 1>,
                         cudaFuncAttributeMaxDynamicSharedMemorySize, SMEM_BYTES);
    cudaFuncSetAttribute(gemm_k<32, false, 0>,
                         cudaFuncAttributeMaxDynamicSharedMemorySize, SMEM_BYTES);

    // converts (fp32 -> fp16)
    conv_all<<<dim3(2048, 10), 256>>>(tgt, mem, pos, Wq, Wkc, Wkp, Wv, Wo, W1, W2, h16);

    dim3 blkG(512);
    dim3 blkA(256);

    // fused q/k/v projections (fp16 out)
    qkv_mma<<<dim3(2, 128, 3), blkG, SMEM_BYTES>>>(
        h16 + OFF_TGT, h16 + OFF_MEM, h16 + OFF_POS,
        h16 + OFF_WQ, h16 + OFF_WKC, h16 + OFF_WKP, h16 + OFF_WV,
        bq, bkc, bkp, bv, q_, k_, v_);
    // attention -> at (fp16)
    attn_kernel<<<NQ / 8, blkA>>>(q_, k_, v_, kbc, ipair, ibatch, h16 + OFF_AT);
    // t2 = at @ Wo^T + bo  (fp32 out)
    gemm_k<8, false, 0><<<dim3(2, 128), blkG, SMEM_BYTES>>>(
        h16 + OFF_AT, h16 + OFF_WO, bo, t2_, nullptr, DM);
    // x = LN(tgt + t2), also fp16 copy
    residual_ln<true><<<NQ / 8, blkA>>>(tgt, t2_, g2, be2, x_, h16 + OFF_X);
    // h = relu(x @ W1^T + b1)  (fp16 out)
    gemm_k<8, true, 1><<<dim3(8, 128), blkG, SMEM_BYTES>>>(
        h16 + OFF_X, h16 + OFF_W1, b1, nullptr, h16 + OFF_H, DFF_);
    // y = h @ W2^T + b2  (fp32 out)
    gemm_k<32, false, 0><<<dim3(2, 128), blkG, SMEM_BYTES>>>(
        h16 + OFF_H, h16 + OFF_W2, b2, t2_, nullptr, DM);
    // out = LN(x + y)
    residual_ln<false><<<NQ / 8, blkA>>>(x_, t2_, g3, be3, out, nullptr);
}

// round 13
// speedup vs baseline: 1.0062x; 1.0062x over previous
#include <cuda_runtime.h>
#include <cuda_fp16.h>
#include <cstdint>

#define NQ 16384
#define DM 256
#define DFF_ 1024
#define LN_EPS 1e-5f

// ---------------------------------------------------------------------------
// scratch
// ---------------------------------------------------------------------------
__device__ float g_f32[1u * NQ * DM];          // x (fp32 residual stream)
__device__ __half g_qkv[3u * NQ * DM];         // q, k, v

// fp16 pool (element offsets)
#define OFF_TGT 0u
#define OFF_MEM 4194304u
#define OFF_POS 8388608u
#define OFF_AT  12582912u
#define OFF_X   16777216u
#define OFF_H   20971520u
#define OFF_WQ  37748736u
#define OFF_WKC 37814272u
#define OFF_WKP 37879808u
#define OFF_WV  37945344u
#define OFF_WO  38010880u
#define OFF_W1  38076416u
#define OFF_W2  38338560u
#define OFF_T2  38600704u
#define TOT_H16 42795008u
__device__ __half g_h16[TOT_H16];

// ---------------------------------------------------------------------------
// helpers
// ---------------------------------------------------------------------------
__device__ __forceinline__ uint32_t smem_u32(const void* p) {
    uint32_t a;
    asm("{ .reg .u64 t; cvta.to.shared.u64 t, %1; cvt.u32.u64 %0, t; }"
        : "=r"(a) : "l"(p));
    return a;
}
__device__ __forceinline__ void cpa16(uint32_t dst, const void* src) {
    asm volatile("cp.async.cg.shared.global [%0], [%1], 16;"
                 :: "r"(dst), "l"(src) : "memory");
}
#define CP_COMMIT() asm volatile("cp.async.commit_group;" ::: "memory")
#define CP_WAIT(n)  asm volatile("cp.async.wait_group %0;" :: "n"(n) : "memory")

#define LDSM4(r, addr) \
    asm volatile("ldmatrix.sync.aligned.m8n8.x4.shared.b16 {%0,%1,%2,%3}, [%4];" \
        : "=r"((r)[0]), "=r"((r)[1]), "=r"((r)[2]), "=r"((r)[3]) : "r"(addr))

#define MMA_F16(d, a, b0, b1) \
    asm volatile("mma.sync.aligned.m16n8k16.row.col.f32.f16.f16.f32 " \
        "{%0,%1,%2,%3}, {%4,%5,%6,%7}, {%8,%9}, {%0,%1,%2,%3};" \
        : "+f"((d)[0]), "+f"((d)[1]), "+f"((d)[2]), "+f"((d)[3]) \
        : "r"((a)[0]), "r"((a)[1]), "r"((a)[2]), "r"((a)[3]), "r"(b0), "r"(b1))

// swizzled smem byte offset for (row, chunk16B) with 64B rows (BK=32 fp16)
__device__ __forceinline__ uint32_t swzoff(int row, int ch) {
    return (uint32_t)(row * 64 + ((ch ^ ((row >> 1) & 3)) << 4));
}

__device__ __forceinline__ uint32_t pack2(float a, float b) {
    __half2 p;
    p.x = __float2half_rn(a);
    p.y = __float2half_rn(b);
    return *(uint32_t*)&p;
}

#define PART_SZ 8192u                // 128 rows * 64B
#define STAGE_SZ 16384u              // A + W
#define NSTAGE 4
#define SMEM_BYTES (NSTAGE * STAGE_SZ)   // 65536

// ---------------------------------------------------------------------------
// GEMM core (512 threads, 16 warps of 32x32): acc += A[bm:+128,:K] @ W[bn:+128,:K]^T
// ---------------------------------------------------------------------------
template <int CHUNKS>
__device__ __forceinline__ void gemm_core(
    uint32_t sbase, const __half* __restrict__ A, const __half* __restrict__ W,
    int bm, int bn, int tid, int wm, int wn, int lane, float (&acc)[2][4][4])
{
    constexpr int K = CHUNKS * 32;
    __syncthreads();   // protect smem reuse from a previous pass

    const int lrow = tid >> 2;
    const int lch = tid & 3;

    auto load = [&](int c) {
        const uint32_t stage = sbase + (uint32_t)(c % NSTAGE) * STAGE_SZ;
        cpa16(stage + swzoff(lrow, lch),
              A + (size_t)(bm + lrow) * K + c * 32 + lch * 8);
        cpa16(stage + PART_SZ + swzoff(lrow, lch),
              W + (size_t)(bn + lrow) * K + c * 32 + lch * 8);
        CP_COMMIT();
    };

    auto comp = [&](int s) {
        const uint32_t stage = sbase + (uint32_t)s * STAGE_SZ;
#pragma unroll
        for (int ks = 0; ks < 2; ++ks) {
            const int ch = ks * 2 + (lane >> 4);
            uint32_t af[2][4], bf[2][4];
#pragma unroll
            for (int mt = 0; mt < 2; ++mt)
                LDSM4(af[mt], stage + swzoff(wm + mt * 16 + (lane & 15), ch));
#pragma unroll
            for (int np = 0; np < 2; ++np)
                LDSM4(bf[np], stage + PART_SZ + swzoff(wn + np * 16 + (lane & 15), ch));
#pragma unroll
            for (int mt = 0; mt < 2; ++mt) {
#pragma unroll
                for (int nt = 0; nt < 4; ++nt) {
                    const int np = nt >> 1;
                    const int o0 = (nt & 1);
                    MMA_F16(acc[mt][nt], af[mt], bf[np][o0], bf[np][o0 + 2]);
                }
            }
        }
    };

#pragma unroll
    for (int c = 0; c < NSTAGE - 1; ++c) load(c);
#pragma unroll
    for (int c = 0; c < CHUNKS; ++c) {
        const int rem = CHUNKS - 1 - c;
        if (rem >= 2) { CP_WAIT(2); }
        else if (rem == 1) { CP_WAIT(1); }
        else { CP_WAIT(0); }
        __syncthreads();
        if (c + NSTAGE - 1 < CHUNKS) load(c + NSTAGE - 1);
        comp(c % NSTAGE);
    }
}

// epilogue: acc + bias (+bias2) [+relu] -> fp32 (0) or fp16 (1)
template <bool RELU, int OUTMODE>
__device__ __forceinline__ void epilogue(
    float (&acc)[2][4][4], const float* __restrict__ bias,
    const float* __restrict__ bias2, float* __restrict__ C,
    __half* __restrict__ Ch, int bm, int bn, int wm, int wn, int lane, int Nout)
{
    float bcol[4][2];
#pragma unroll
    for (int nt = 0; nt < 4; ++nt) {
        int col = bn + wn + nt * 8 + (lane & 3) * 2;
        float b0 = bias[col], b1 = bias[col + 1];
        if (bias2) { b0 += bias2[col]; b1 += bias2[col + 1]; }
        bcol[nt][0] = b0; bcol[nt][1] = b1;
    }
#pragma unroll
    for (int mt = 0; mt < 2; ++mt) {
        int row0 = bm + wm + mt * 16 + (lane >> 2);
#pragma unroll
        for (int nt = 0; nt < 4; ++nt) {
            int col = bn + wn + nt * 8 + (lane & 3) * 2;
#pragma unroll
            for (int half = 0; half < 2; ++half) {
                int row = row0 + half * 8;
                float v0 = acc[mt][nt][half * 2 + 0] + bcol[nt][0];
                float v1 = acc[mt][nt][half * 2 + 1] + bcol[nt][1];
                if (RELU) { v0 = fmaxf(v0, 0.f); v1 = fmaxf(v1, 0.f); }
                size_t go = (size_t)row * Nout + col;
                if (OUTMODE == 1) {
                    *(uint32_t*)(Ch + go) = pack2(v0, v1);
                } else {
                    *(float2*)(C + go) = make_float2(v0, v1);
                }
            }
        }
    }
}

// ---------------------------------------------------------------------------
// Fused q/k/v projection: grid (2, 128, 3); z selects q, k(dual), v. 512 thr.
// ---------------------------------------------------------------------------
__global__ __launch_bounds__(512, 2)
void qkv_mma(const __half* __restrict__ tgtH, const __half* __restrict__ memH,
             const __half* __restrict__ posH,
             const __half* __restrict__ WqH, const __half* __restrict__ WkcH,
             const __half* __restrict__ WkpH, const __half* __restrict__ WvH,
             const float* __restrict__ bq, const float* __restrict__ bkc,
             const float* __restrict__ bkp, const float* __restrict__ bv,
             __half* __restrict__ q_, __half* __restrict__ k_,
             __half* __restrict__ v_)
{
    extern __shared__ char smem[];
    const uint32_t sbase = smem_u32(smem);
    const int tid = threadIdx.x;
    const int wid = tid >> 5;
    const int lane = tid & 31;
    const int bm = blockIdx.y * 128;
    const int bn = blockIdx.x * 128;
    const int wm = (wid & 3) * 32;
    const int wn = (wid >> 2) * 32;
    const int z = blockIdx.z;

    float acc[2][4][4];
#pragma unroll
    for (int a = 0; a < 2; ++a)
#pragma unroll
        for (int b = 0; b < 4; ++b)
#pragma unroll
            for (int c = 0; c < 4; ++c) acc[a][b][c] = 0.f;

    const __half* A = (z == 0) ? tgtH : memH;
    const __half* W = (z == 0) ? WqH : (z == 1) ? WkcH : WvH;
    gemm_core<8>(sbase, A, W, bm, bn, tid, wm, wn, lane, acc);
    if (z == 1)
        gemm_core<8>(sbase, posH, WkpH, bm, bn, tid, wm, wn, lane, acc);

    const float* bias = (z == 0) ? bq : (z == 1) ? bkc : bv;
    const float* bias2 = (z == 1) ? bkp : nullptr;
    __half* out = (z == 0) ? q_ : (z == 1) ? k_ : v_;
    epilogue<false, 1>(acc, bias, bias2, nullptr, out, bm, bn, wm, wn, lane, DM);
}

// ---------------------------------------------------------------------------
// Generic GEMM launch: C = A@W^T + bias  (512 threads)
// ---------------------------------------------------------------------------
template <int CHUNKS, bool RELU, int OUTMODE>
__global__ __launch_bounds__(512, 2)
void gemm_k(const __half* __restrict__ A, const __half* __restrict__ W,
            const float* __restrict__ bias,
            float* __restrict__ C, __half* __restrict__ Ch, int Nout)
{
    extern __shared__ char smem[];
    const uint32_t sbase = smem_u32(smem);
    const int tid = threadIdx.x;
    const int wid = tid >> 5;
    const int lane = tid & 31;
    const int bm = blockIdx.y * 128;
    const int bn = blockIdx.x * 128;
    const int wm = (wid & 3) * 32;
    const int wn = (wid >> 2) * 32;

    float acc[2][4][4];
#pragma unroll
    for (int a = 0; a < 2; ++a)
#pragma unroll
        for (int b = 0; b < 4; ++b)
#pragma unroll
            for (int c = 0; c < 4; ++c) acc[a][b][c] = 0.f;

    gemm_core<CHUNKS>(sbase, A, W, bm, bn, tid, wm, wn, lane, acc);
    epilogue<RELU, OUTMODE>(acc, bias, nullptr, C, Ch, bm, bn, wm, wn, lane, Nout);
}

// ---------------------------------------------------------------------------
// Conversion: fp32 -> fp16, 10 tensors via blockIdx.y, 8 elems/thread
// ---------------------------------------------------------------------------
__global__ __launch_bounds__(256)
void conv_all(const float* s0, const float* s1, const float* s2, const float* s3,
              const float* s4, const float* s5, const float* s6, const float* s7,
              const float* s8, const float* s9, __half* dst)
{
    const int t = blockIdx.y;
    const unsigned narr[10] = {4194304u, 4194304u, 4194304u, 65536u, 65536u,
                               65536u, 65536u, 65536u, 262144u, 262144u};
    const unsigned offarr[10] = {OFF_TGT, OFF_MEM, OFF_POS, OFF_WQ, OFF_WKC,
                                 OFF_WKP, OFF_WV, OFF_WO, OFF_W1, OFF_W2};
    const float* srcs[10] = {s0, s1, s2, s3, s4, s5, s6, s7, s8, s9};
    unsigned i = (blockIdx.x * 256u + threadIdx.x) * 8u;
    if (i >= narr[t]) return;
    const float* src = srcs[t];
    float4 v0 = *(const float4*)(src + i);
    float4 v1 = *(const float4*)(src + i + 4);
    uint4 o;
    o.x = pack2(v0.x, v0.y);
    o.y = pack2(v0.z, v0.w);
    o.z = pack2(v1.x, v1.y);
    o.w = pack2(v1.z, v1.w);
    *(uint4*)(dst + offarr[t] + i) = o;
}

// ---------------------------------------------------------------------------
// Local attention: one warp per query; q/k/v fp16, output fp16.
// ---------------------------------------------------------------------------
__global__ __launch_bounds__(256, 2)
void attn_kernel(const __half* __restrict__ q, const __half* __restrict__ k,
                 const __half* __restrict__ v, const int* __restrict__ kbc,
                 const int* __restrict__ ipair, const int* __restrict__ ibatch,
                 __half* __restrict__ oat)
{
    __shared__ int sg[8][32];
    const int warp = threadIdx.x >> 5;
    const int lane = threadIdx.x & 31;
    const int n = blockIdx.x * 8 + warp;
    const int h = lane >> 2;
    const int s = lane & 3;
    const int doff = h * 32 + s * 8;

    int b = ibatch[n];
    int off = 0;
    for (int i = 0; i < b; ++i) off += kbc[i];

    int idx = ipair[n * 32 + lane];
    unsigned mb = __ballot_sync(0xffffffffu, idx < 0);
    sg[warp][lane] = ((idx < 0) ? 0 : idx) + off;
    __syncwarp();

    const float scale = 0.17677669529663687f;
    float qr[8];
    {
        uint4 raw = *(const uint4*)&q[(size_t)n * 256 + doff];
        float2 a0 = __half22float2(*(__half2*)&raw.x);
        float2 a1 = __half22float2(*(__half2*)&raw.y);
        float2 a2 = __half22float2(*(__half2*)&raw.z);
        float2 a3 = __half22float2(*(__half2*)&raw.w);
        qr[0] = a0.x * scale; qr[1] = a0.y * scale;
        qr[2] = a1.x * scale; qr[3] = a1.y * scale;
        qr[4] = a2.x * scale; qr[5] = a2.y * scale;
        qr[6] = a3.x * scale; qr[7] = a3.y * scale;
    }

    float lg[32];
#pragma unroll
    for (int jb = 0; jb < 32; jb += 8) {
        uint4 raw[8];
#pragma unroll
        for (int u = 0; u < 8; ++u)
            raw[u] = *(const uint4*)&k[(size_t)sg[warp][jb + u] * 256 + doff];
#pragma unroll
        for (int u = 0; u < 8; ++u) {
            float2 a0 = __half22float2(*(__half2*)&raw[u].x);
            float2 a1 = __half22float2(*(__half2*)&raw[u].y);
            float2 a2 = __half22float2(*(__half2*)&raw[u].z);
            float2 a3 = __half22float2(*(__half2*)&raw[u].w);
            float t = qr[0] * a0.x + qr[1] * a0.y + qr[2] * a1.x + qr[3] * a1.y
                    + qr[4] * a2.x + qr[5] * a2.y + qr[6] * a3.x + qr[7] * a3.y;
            t += __shfl_xor_sync(0xffffffffu, t, 1);
            t += __shfl_xor_sync(0xffffffffu, t, 2);
            lg[jb + u] = ((mb >> (jb + u)) & 1u) ? -1e9f : t;
        }
    }

    float m = lg[0];
#pragma unroll
    for (int j = 1; j < 32; ++j) m = fmaxf(m, lg[j]);
    float sum = 0.f;
#pragma unroll
    for (int j = 0; j < 32; ++j) { lg[j] = __expf(lg[j] - m); sum += lg[j]; }
    float rinv = 1.f / sum;

    float acc[8];
#pragma unroll
    for (int i = 0; i < 8; ++i) acc[i] = 0.f;
#pragma unroll
    for (int jb = 0; jb < 32; jb += 8) {
        uint4 raw[8];
#pragma unroll
        for (int u = 0; u < 8; ++u)
            raw[u] = *(const uint4*)&v[(size_t)sg[warp][jb + u] * 256 + doff];
#pragma unroll
        for (int u = 0; u < 8; ++u) {
            float2 a0 = __half22float2(*(__half2*)&raw[u].x);
            float2 a1 = __half22float2(*(__half2*)&raw[u].y);
            float2 a2 = __half22float2(*(__half2*)&raw[u].z);
            float2 a3 = __half22float2(*(__half2*)&raw[u].w);
            float p = lg[jb + u] * rinv;
            acc[0] += p * a0.x; acc[1] += p * a0.y;
            acc[2] += p * a1.x; acc[3] += p * a1.y;
            acc[4] += p * a2.x; acc[5] += p * a2.y;
            acc[6] += p * a3.x; acc[7] += p * a3.y;
        }
    }

    uint4 o;
    o.x = pack2(acc[0], acc[1]);
    o.y = pack2(acc[2], acc[3]);
    o.z = pack2(acc[4], acc[5]);
    o.w = pack2(acc[6], acc[7]);
    *(uint4*)(oat + (size_t)n * 256 + doff) = o;
}

// ---------------------------------------------------------------------------
// out = LayerNorm(a + b); a fp32, b fp16. optionally also writes fp16 copy.
// ---------------------------------------------------------------------------
template <bool OUTH>
__global__ __launch_bounds__(256)
void residual_ln(const float* __restrict__ a, const __half* __restrict__ bsrc,
                 const float* __restrict__ g, const float* __restrict__ be,
                 float* __restrict__ out, __half* __restrict__ oh)
{
    const int warp = threadIdx.x >> 5;
    const int lane = threadIdx.x & 31;
    const int n = blockIdx.x * 8 + warp;
    const int base = lane * 8;

    float x[8];
    {
        const float4* pa0 = (const float4*)&a[(size_t)n * 256 + base];
        float4 a0 = pa0[0], a1 = pa0[1];
        uint4 braw = *(const uint4*)&bsrc[(size_t)n * 256 + base];
        float2 b0 = __half22float2(*(__half2*)&braw.x);
        float2 b1 = __half22float2(*(__half2*)&braw.y);
        float2 b2 = __half22float2(*(__half2*)&braw.z);
        float2 b3 = __half22float2(*(__half2*)&braw.w);
        x[0] = a0.x + b0.x; x[1] = a0.y + b0.y; x[2] = a0.z + b1.x; x[3] = a0.w + b1.y;
        x[4] = a1.x + b2.x; x[5] = a1.y + b2.y; x[6] = a1.z + b3.x; x[7] = a1.w + b3.y;
    }
    float s = 0.f;
#pragma unroll
    for (int i = 0; i < 8; ++i) s += x[i];
#pragma unroll
    for (int o = 16; o > 0; o >>= 1) s += __shfl_xor_sync(0xffffffffu, s, o);
    float mean = s * (1.f / 256.f);

    float vs = 0.f;
#pragma unroll
    for (int i = 0; i < 8; ++i) { float d = x[i] - mean; vs += d * d; }
#pragma unroll
    for (int o = 16; o > 0; o >>= 1) vs += __shfl_xor_sync(0xffffffffu, vs, o);
    float inv = rsqrtf(vs * (1.f / 256.f) + LN_EPS);

    float4 gg0 = *(const float4*)&g[base];
    float4 gg1 = *(const float4*)&g[base + 4];
    float4 bb0 = *(const float4*)&be[base];
    float4 bb1 = *(const float4*)&be[base + 4];

    float r[8];
    r[0] = (x[0] - mean) * inv * gg0.x + bb0.x;
    r[1] = (x[1] - mean) * inv * gg0.y + bb0.y;
    r[2] = (x[2] - mean) * inv * gg0.z + bb0.z;
    r[3] = (x[3] - mean) * inv * gg0.w + bb0.w;
    r[4] = (x[4] - mean) * inv * gg1.x + bb1.x;
    r[5] = (x[5] - mean) * inv * gg1.y + bb1.y;
    r[6] = (x[6] - mean) * inv * gg1.z + bb1.z;
    r[7] = (x[7] - mean) * inv * gg1.w + bb1.w;

    size_t o = (size_t)n * 256 + base;
    *(float4*)(out + o) = make_float4(r[0], r[1], r[2], r[3]);
    *(float4*)(out + o + 4) = make_float4(r[4], r[5], r[6], r[7]);

    if (OUTH) {
        uint4 p;
        p.x = pack2(r[0], r[1]);
        p.y = pack2(r[2], r[3]);
        p.z = pack2(r[4], r[5]);
        p.w = pack2(r[6], r[7]);
        *(uint4*)(oh + o) = p;
    }
}

// ---------------------------------------------------------------------------
extern "C" void kernel_launch(void* const* d_in, const int* in_sizes, int n_in,
                              void* d_out, int out_size)
{
    const float* tgt  = (const float*)d_in[0];
    const float* mem  = (const float*)d_in[1];
    const float* pos  = (const float*)d_in[2];
    const int*   kbc  = (const int*)d_in[3];
    const int*   ipair  = (const int*)d_in[4];
    const int*   ibatch = (const int*)d_in[5];
    const float* Wq  = (const float*)d_in[6];
    const float* bq  = (const float*)d_in[7];
    const float* Wkc = (const float*)d_in[8];
    const float* bkc = (const float*)d_in[9];
    const float* Wkp = (const float*)d_in[10];
    const float* bkp = (const float*)d_in[11];
    const float* Wv  = (const float*)d_in[12];
    const float* bv  = (const float*)d_in[13];
    const float* Wo  = (const float*)d_in[14];
    const float* bo  = (const float*)d_in[15];
    const float* W1  = (const float*)d_in[16];
    const float* b1  = (const float*)d_in[17];
    const float* W2  = (const float*)d_in[18];
    const float* b2  = (const float*)d_in[19];
    const float* g2  = (const float*)d_in[20];
    const float* be2 = (const float*)d_in[21];
    const float* g3  = (const float*)d_in[22];
    const float* be3 = (const float*)d_in[23];
    float* out = (float*)d_out;

    float* f32 = nullptr;
    __half* qkv = nullptr;
    __half* h16 = nullptr;
    cudaGetSymbolAddress((void**)&f32, g_f32);
    cudaGetSymbolAddress((void**)&qkv, g_qkv);
    cudaGetSymbolAddress((void**)&h16, g_h16);

    float* x_  = f32;
    __half* q_ = qkv + 0u * NQ * DM;
    __half* k_ = qkv + 1u * NQ * DM;
    __half* v_ = qkv + 2u * NQ * DM;
    __half* t2h = h16 + OFF_T2;

    cudaFuncSetAttribute(qkv_mma,
                         cudaFuncAttributeMaxDynamicSharedMemorySize, SMEM_BYTES);
    cudaFuncSetAttribute(gemm_k<8, false, 1>,
                         cudaFuncAttributeMaxDynamicSharedMemorySize, SMEM_BYTES);
    cudaFuncSetAttribute(gemm_k<8, true, 1>,
                         cudaFuncAttributeMaxDynamicSharedMemorySize, SMEM_BYTES);
    cudaFuncSetAttribute(gemm_k<32, false, 1>,
                         cudaFuncAttributeMaxDynamicSharedMemorySize, SMEM_BYTES);

    // converts (fp32 -> fp16)
    conv_all<<<dim3(2048, 10), 256>>>(tgt, mem, pos, Wq, Wkc, Wkp, Wv, Wo, W1, W2, h16);

    dim3 blkG(512);
    dim3 blkA(256);

    // fused q/k/v projections (fp16 out)
    qkv_mma<<<dim3(2, 128, 3), blkG, SMEM_BYTES>>>(
        h16 + OFF_TGT, h16 + OFF_MEM, h16 + OFF_POS,
        h16 + OFF_WQ, h16 + OFF_WKC, h16 + OFF_WKP, h16 + OFF_WV,
        bq, bkc, bkp, bv, q_, k_, v_);
    // attention -> at (fp16)
    attn_kernel<<<NQ / 8, blkA>>>(q_, k_, v_, kbc, ipair, ibatch, h16 + OFF_AT);
    // t2 = at @ Wo^T + bo  (fp16 out)
    gemm_k<8, false, 1><<<dim3(2, 128), blkG, SMEM_BYTES>>>(
        h16 + OFF_AT, h16 + OFF_WO, bo, nullptr, t2h, DM);
    // x = LN(tgt + t2), fp32 + fp16 copy
    residual_ln<true><<<NQ / 8, blkA>>>(tgt, t2h, g2, be2, x_, h16 + OFF_X);
    // h = relu(x @ W1^T + b1)  (fp16 out)
    gemm_k<8, true, 1><<<dim3(8, 128), blkG, SMEM_BYTES>>>(
        h16 + OFF_X, h16 + OFF_W1, b1, nullptr, h16 + OFF_H, DFF_);
    // y = h @ W2^T + b2  (fp16 out)
    gemm_k<32, false, 1><<<dim3(2, 128), blkG, SMEM_BYTES>>>(
        h16 + OFF_H, h16 + OFF_W2, b2, nullptr, t2h, DM);
    // out = LN(x + y)
    residual_ln<false><<<NQ / 8, blkA>>>(x_, t2h, g3, be3, out, nullptr);
}